// round 7
// baseline (speedup 1.0000x reference)
#include <cuda_runtime.h>
#include <cstdint>
#include <cstddef>

#define D_MODEL 1024
#define FF_DIM  1024
#define BATCH   8
#define SEQ     2048
#define M_TOTAL (BATCH * SEQ)      // 16384
#define ATTN_SCALE 0.03125f

// ---- GEMM tile config ------------------------------------------------------
#define BM 128
#define BN 256
#define BK 32
#define AS_STRIDE 36                         // 32 data + 4 pad words -> conflict-free frags
#define A_TILE_WORDS (128 * AS_STRIDE)       // 4608
#define B_TILE_WORDS (256 * AS_STRIDE)       // 9216
#define STAGE_WORDS (A_TILE_WORDS + B_TILE_WORDS)   // 13824
#define SMEM_WORDS  (2 * STAGE_WORDS)        // 2 stages
#define SMEM_BYTES  (SMEM_WORDS * 4)         // 110592 B

// ---- scratch (device globals; no runtime allocation) -----------------------
__device__ float g_x[(size_t)M_TOTAL * D_MODEL];          // rounded X
__device__ float g_w[3][(size_t)FF_DIM * D_MODEL];        // rounded Wq/Wk/Wv
__device__ float g_q[(size_t)M_TOTAL * FF_DIM];           // rounded Q
__device__ float g_k[(size_t)M_TOTAL * FF_DIM];           // rounded K
__device__ float g_v[(size_t)M_TOTAL * FF_DIM];           // V (fp32)
__device__ float g_vT[(size_t)BATCH * FF_DIM * SEQ];      // rounded V^T
__device__ float g_s[(size_t)BATCH * SEQ * SEQ];          // scores / P

// ---- helpers ---------------------------------------------------------------
__device__ __forceinline__ uint32_t smem_u32(const void* p) {
    uint32_t a;
    asm("{ .reg .u64 t; cvta.to.shared.u64 t, %1; cvt.u32.u64 %0, t; }"
        : "=r"(a) : "l"(p));
    return a;
}

__device__ __forceinline__ float rna_tf32(float x) {
    uint32_t r; asm("cvt.rna.tf32.f32 %0, %1;" : "=r"(r) : "f"(x));
    return __uint_as_float(r);
}

__device__ __forceinline__ void cp_async16(uint32_t dst, const void* src) {
    asm volatile("cp.async.cg.shared.global [%0], [%1], 16;"
                 :: "r"(dst), "l"(src));
}
#define CP_COMMIT() asm volatile("cp.async.commit_group;" ::: "memory")
#define CP_WAIT(n)  asm volatile("cp.async.wait_group %0;" :: "n"(n) : "memory")

__device__ __forceinline__ void mma_tf32(float* d, const uint32_t* a, const uint32_t* b) {
    asm volatile(
        "mma.sync.aligned.m16n8k8.row.col.f32.tf32.tf32.f32 "
        "{%0,%1,%2,%3}, {%4,%5,%6,%7}, {%8,%9}, {%0,%1,%2,%3};"
        : "+f"(d[0]), "+f"(d[1]), "+f"(d[2]), "+f"(d[3])
        : "r"(a[0]), "r"(a[1]), "r"(a[2]), "r"(a[3]), "r"(b[0]), "r"(b[1]));
}

// ---------------------------------------------------------------------------
// tf32 tensor-core GEMM (NT): C[m,n] = scale * sum_k A[m,k]*B[n,k] + bias[n]
// A: [M,K] row-major, B: [N,K] row-major. 256 threads, 8 warps (2m x 4n),
// warp tile 64x64, block tile 128x256, 2-stage cp.async double buffer.
// ---------------------------------------------------------------------------
__device__ __forceinline__ void gemm_core(
    const float* __restrict__ A, int lda,
    const float* __restrict__ B, int ldb,
    float* __restrict__ C, int ldc,
    int K, const float* __restrict__ bias, float scale, bool do_round)
{
    extern __shared__ float smem[];
    const int tid  = threadIdx.x;
    const int wid  = tid >> 5;
    const int lane = tid & 31;
    const int wm   = wid >> 2;          // 0..1  -> 64-row slab
    const int wn   = wid & 3;           // 0..3  -> 64-col slab
    const int g    = lane >> 2;         // 0..7
    const int c    = lane & 3;          // 0..3
    const int m0   = blockIdx.y * BM;
    const int n0   = blockIdx.x * BN;
    const int NT   = K >> 5;

    float acc[4][8][4];
    #pragma unroll
    for (int i = 0; i < 4; i++)
        #pragma unroll
        for (int j = 0; j < 8; j++)
            #pragma unroll
            for (int r = 0; r < 4; r++) acc[i][j][r] = 0.0f;

    // producer mapping:
    //   A: 2 threads per 32-float row (4 x 16B each), rows 0..127
    //   B: 1 thread per 32-float row (8 x 16B each), rows 0..255
    const int aprow = tid >> 1;
    const int apcol = (tid & 1) * 16;
    const float* Ag = A + (size_t)(m0 + aprow) * lda + apcol;
    const float* Bg = B + (size_t)(n0 + tid) * ldb;
    const uint32_t sb = smem_u32(smem);
    const uint32_t a_dst = sb + (uint32_t)(aprow * AS_STRIDE + apcol) * 4;
    const uint32_t b_dst = sb + (uint32_t)(A_TILE_WORDS + tid * AS_STRIDE) * 4;

    // prologue: stage 0
    {
        #pragma unroll
        for (int j = 0; j < 4; j++)
            cp_async16(a_dst + j * 16, Ag + j * 4);
        #pragma unroll
        for (int j = 0; j < 8; j++)
            cp_async16(b_dst + j * 16, Bg + j * 4);
        CP_COMMIT();
    }

    for (int t = 0; t < NT; t++) {
        if (t + 1 < NT) {
            const uint32_t so = (uint32_t)(((t + 1) & 1) * STAGE_WORDS) * 4;
            const float* ag = Ag + (t + 1) * BK;
            const float* bg = Bg + (t + 1) * BK;
            #pragma unroll
            for (int j = 0; j < 4; j++)
                cp_async16(a_dst + so + j * 16, ag + j * 4);
            #pragma unroll
            for (int j = 0; j < 8; j++)
                cp_async16(b_dst + so + j * 16, bg + j * 4);
            CP_COMMIT();
            CP_WAIT(1);
        } else {
            CP_WAIT(0);
        }
        __syncthreads();

        const float* As = smem + (t & 1) * STAGE_WORDS;
        const float* Bs = As + A_TILE_WORDS;

        #pragma unroll
        for (int ks = 0; ks < 4; ks++) {
            const int kb = ks * 8;
            uint32_t af[4][4], bf[8][2];
            #pragma unroll
            for (int mt = 0; mt < 4; mt++) {
                const float* ap = As + (wm * 64 + mt * 16 + g) * AS_STRIDE + kb + c;
                af[mt][0] = __float_as_uint(ap[0]);
                af[mt][1] = __float_as_uint(ap[8 * AS_STRIDE]);
                af[mt][2] = __float_as_uint(ap[4]);
                af[mt][3] = __float_as_uint(ap[8 * AS_STRIDE + 4]);
            }
            #pragma unroll
            for (int nt = 0; nt < 8; nt++) {
                const float* bp = Bs + (wn * 64 + nt * 8 + g) * AS_STRIDE + kb + c;
                bf[nt][0] = __float_as_uint(bp[0]);
                bf[nt][1] = __float_as_uint(bp[4]);
            }
            #pragma unroll
            for (int mt = 0; mt < 4; mt++)
                #pragma unroll
                for (int nt = 0; nt < 8; nt++)
                    mma_tf32(acc[mt][nt], af[mt], bf[nt]);
        }
        __syncthreads();
    }

    // epilogue
    #pragma unroll
    for (int mt = 0; mt < 4; mt++) {
        #pragma unroll
        for (int nt = 0; nt < 8; nt++) {
            const int row0 = m0 + wm * 64 + mt * 16 + g;
            const int col  = n0 + wn * 64 + nt * 8 + 2 * c;
            const float b0 = bias ? bias[col]     : 0.0f;
            const float b1 = bias ? bias[col + 1] : 0.0f;
            #pragma unroll
            for (int h = 0; h < 2; h++) {
                float x0 = acc[mt][nt][2 * h + 0] * scale + b0;
                float x1 = acc[mt][nt][2 * h + 1] * scale + b1;
                if (do_round) { x0 = rna_tf32(x0); x1 = rna_tf32(x1); }
                float2 o; o.x = x0; o.y = x1;
                *(float2*)(C + (size_t)(row0 + h * 8) * ldc + col) = o;
            }
        }
    }
}

// ---------------------------------------------------------------------------
// GEMM entry kernels
// ---------------------------------------------------------------------------
__global__ __launch_bounds__(256, 1) void qkv_tc(
    const float* __restrict__ bq, const float* __restrict__ bk,
    const float* __restrict__ bv)
{
    const int z = blockIdx.z;
    const float* W = g_w[z];
    const float* bias = (z == 0) ? bq : (z == 1) ? bk : bv;
    float* O = (z == 0) ? g_q : (z == 1) ? g_k : g_v;
    gemm_core(g_x, D_MODEL, W, D_MODEL, O, FF_DIM, D_MODEL, bias, 1.0f, z < 2);
}

__global__ __launch_bounds__(256, 1) void scores_tc()
{
    const int b = blockIdx.z;
    gemm_core(g_q + (size_t)b * SEQ * FF_DIM, FF_DIM,
              g_k + (size_t)b * SEQ * FF_DIM, FF_DIM,
              g_s + (size_t)b * SEQ * SEQ,    SEQ,
              FF_DIM, nullptr, ATTN_SCALE, false);
}

__global__ __launch_bounds__(256, 1) void pv_tc(float* __restrict__ out)
{
    const int b = blockIdx.z;
    gemm_core(g_s  + (size_t)b * SEQ * SEQ,    SEQ,
              g_vT + (size_t)b * FF_DIM * SEQ, SEQ,
              out  + (size_t)b * SEQ * FF_DIM, FF_DIM,
              SEQ, nullptr, 1.0f, false);
}

// ---------------------------------------------------------------------------
// Prep: round X / W to tf32 (RN) into scratch
// ---------------------------------------------------------------------------
__global__ void round_kernel(const float* __restrict__ src, int which, int n4)
{
    float* dst = (which == 0) ? g_x : g_w[which - 1];
    int i = blockIdx.x * blockDim.x + threadIdx.x;
    if (i < n4) {
        float4 v = ((const float4*)src)[i];
        v.x = rna_tf32(v.x); v.y = rna_tf32(v.y);
        v.z = rna_tf32(v.z); v.w = rna_tf32(v.w);
        ((float4*)dst)[i] = v;
    }
}

// ---------------------------------------------------------------------------
// V transpose (per batch): g_vT[b][f][s] = rna(g_v[b][s][f])
// ---------------------------------------------------------------------------
__global__ void transpose_v()
{
    __shared__ float t[32][33];
    const int b  = blockIdx.z;
    const int s0 = blockIdx.x * 32;
    const int f0 = blockIdx.y * 32;
    const int tx = threadIdx.x, ty = threadIdx.y;

    #pragma unroll
    for (int i = 0; i < 4; i++) {
        int s = s0 + ty + i * 8;
        t[ty + i * 8][tx] = g_v[((size_t)b * SEQ + s) * FF_DIM + f0 + tx];
    }
    __syncthreads();
    #pragma unroll
    for (int i = 0; i < 4; i++) {
        int f = f0 + ty + i * 8;
        g_vT[((size_t)b * FF_DIM + f) * SEQ + s0 + tx] = rna_tf32(t[tx][ty + i * 8]);
    }
}

// ---------------------------------------------------------------------------
// Row softmax over g_s rows (len 2048), output rounded to tf32
// ---------------------------------------------------------------------------
__global__ __launch_bounds__(256) void softmax_kernel()
{
    const int row = blockIdx.x;
    float* p = g_s + (size_t)row * SEQ;
    const int tid  = threadIdx.x;
    const int lane = tid & 31;
    const int wid  = tid >> 5;
    __shared__ float red[32];

    float v[8];
    #pragma unroll
    for (int i = 0; i < 8; i++) v[i] = p[tid + i * 256];

    float m = v[0];
    #pragma unroll
    for (int i = 1; i < 8; i++) m = fmaxf(m, v[i]);
    #pragma unroll
    for (int o = 16; o > 0; o >>= 1) m = fmaxf(m, __shfl_xor_sync(0xffffffffu, m, o));
    if (lane == 0) red[wid] = m;
    __syncthreads();
    if (tid < 32) {
        float t = (lane < 8) ? red[lane] : -3.4e38f;
        #pragma unroll
        for (int o = 4; o > 0; o >>= 1) t = fmaxf(t, __shfl_xor_sync(0xffffffffu, t, o));
        red[lane] = t;
    }
    __syncthreads();
    m = red[0];
    __syncthreads();

    float s = 0.0f;
    #pragma unroll
    for (int i = 0; i < 8; i++) { v[i] = __expf(v[i] - m); s += v[i]; }
    #pragma unroll
    for (int o = 16; o > 0; o >>= 1) s += __shfl_xor_sync(0xffffffffu, s, o);
    if (lane == 0) red[wid] = s;
    __syncthreads();
    if (tid < 32) {
        float t = (lane < 8) ? red[lane] : 0.0f;
        #pragma unroll
        for (int o = 4; o > 0; o >>= 1) t += __shfl_xor_sync(0xffffffffu, t, o);
        red[lane] = t;
    }
    __syncthreads();
    const float inv = 1.0f / red[0];

    #pragma unroll
    for (int i = 0; i < 8; i++) p[tid + i * 256] = rna_tf32(v[i] * inv);
}

// ---------------------------------------------------------------------------
// Entry point
// ---------------------------------------------------------------------------
extern "C" void kernel_launch(void* const* d_in, const int* in_sizes, int n_in,
                              void* d_out, int out_size)
{
    const float* seq = (const float*)d_in[0];
    const float* Wq  = (const float*)d_in[1];
    const float* bq  = (const float*)d_in[2];
    const float* Wk  = (const float*)d_in[3];
    const float* bk  = (const float*)d_in[4];
    const float* Wv  = (const float*)d_in[5];
    const float* bv  = (const float*)d_in[6];
    float* out = (float*)d_out;

    // idempotent every call (no static guards allowed)
    cudaFuncSetAttribute(qkv_tc,    cudaFuncAttributeMaxDynamicSharedMemorySize, SMEM_BYTES);
    cudaFuncSetAttribute(scores_tc, cudaFuncAttributeMaxDynamicSharedMemorySize, SMEM_BYTES);
    cudaFuncSetAttribute(pv_tc,     cudaFuncAttributeMaxDynamicSharedMemorySize, SMEM_BYTES);

    // 1) round inputs to tf32 (RN)
    const int nx4 = (M_TOTAL * D_MODEL) / 4;
    const int nw4 = (FF_DIM * D_MODEL) / 4;
    round_kernel<<<(nx4 + 255) / 256, 256>>>(seq, 0, nx4);
    round_kernel<<<(nw4 + 255) / 256, 256>>>(Wq, 1, nw4);
    round_kernel<<<(nw4 + 255) / 256, 256>>>(Wk, 2, nw4);
    round_kernel<<<(nw4 + 255) / 256, 256>>>(Wv, 3, nw4);

    // 2) Q/K/V projections (tensor core)
    qkv_tc<<<dim3(FF_DIM / BN, M_TOTAL / BM, 3), 256, SMEM_BYTES>>>(bq, bk, bv);

    // 3) V^T (rounded) for the PV GEMM
    transpose_v<<<dim3(SEQ / 32, FF_DIM / 32, BATCH), dim3(32, 8)>>>();

    // 4) scores = scale * Q K^T
    scores_tc<<<dim3(SEQ / BN, SEQ / BM, BATCH), 256, SMEM_BYTES>>>();

    // 5) softmax (rounded output)
    softmax_kernel<<<M_TOTAL, 256>>>();

    // 6) out = P V
    pv_tc<<<dim3(FF_DIM / BN, SEQ / BM, BATCH), 256, SMEM_BYTES>>>(out);
}

// round 9
// speedup vs baseline: 2.0348x; 2.0348x over previous
#include <cuda_runtime.h>
#include <cuda_fp16.h>
#include <cstdint>
#include <cstddef>

#define D_MODEL 1024
#define FF_DIM  1024
#define BATCH   8
#define SEQ     2048
#define M_TOTAL (BATCH * SEQ)      // 16384
#define ATTN_SCALE 0.03125f

// ---- GEMM tile config (fp16 m16n8k16) --------------------------------------
#define BM 128
#define BN 128
#define BK 64
#define SH 72                                 // halves per smem row (64 data + 8 pad)
#define ROW_WORDS 36                          // 32-bit words per row
#define A_TILE_HALVES (128 * SH)              // 9216 halves (18432 B)
#define STAGE_HALVES (2 * A_TILE_HALVES)      // A + B
#define SMEM_BYTES (2 * STAGE_HALVES * 2)     // 2 stages -> 73728 B

// ---- scratch (device globals; no runtime allocation) -----------------------
__device__ __half g_xh[(size_t)M_TOTAL * D_MODEL];
__device__ __half g_wh[3][(size_t)FF_DIM * D_MODEL];
__device__ __half g_qh[(size_t)M_TOTAL * FF_DIM];
__device__ __half g_kh[(size_t)M_TOTAL * FF_DIM];
__device__ __half g_vh[(size_t)M_TOTAL * FF_DIM];
__device__ __half g_vTh[(size_t)BATCH * FF_DIM * SEQ];
__device__ float  g_s[(size_t)BATCH * SEQ * SEQ];     // fp32 scores
__device__ __half g_p[(size_t)BATCH * SEQ * SEQ];     // half probabilities

// ---- helpers ---------------------------------------------------------------
__device__ __forceinline__ uint32_t smem_u32(const void* p) {
    uint32_t a;
    asm("{ .reg .u64 t; cvta.to.shared.u64 t, %1; cvt.u32.u64 %0, t; }"
        : "=r"(a) : "l"(p));
    return a;
}

__device__ __forceinline__ void cp_async16(uint32_t dst, const void* src) {
    asm volatile("cp.async.cg.shared.global [%0], [%1], 16;"
                 :: "r"(dst), "l"(src));
}
#define CP_COMMIT() asm volatile("cp.async.commit_group;" ::: "memory")
#define CP_WAIT(n)  asm volatile("cp.async.wait_group %0;" :: "n"(n) : "memory")

__device__ __forceinline__ void mma_f16(float* d, const uint32_t* a, const uint32_t* b) {
    asm volatile(
        "mma.sync.aligned.m16n8k16.row.col.f32.f16.f16.f32 "
        "{%0,%1,%2,%3}, {%4,%5,%6,%7}, {%8,%9}, {%0,%1,%2,%3};"
        : "+f"(d[0]), "+f"(d[1]), "+f"(d[2]), "+f"(d[3])
        : "r"(a[0]), "r"(a[1]), "r"(a[2]), "r"(a[3]), "r"(b[0]), "r"(b[1]));
}

// ---------------------------------------------------------------------------
// fp16 tensor-core GEMM (NT): C[m,n] = scale * sum_k A[m,k]*B[n,k] + bias[n]
// A: [M,K] row-major half, B: [N,K] row-major half. 256 threads, 8 warps
// (2m x 4n), warp tile 64x32, BK=64, 2-stage cp.async double buffer.
// Output: Cf (fp32) or Ch (half), exactly one non-null.
// ---------------------------------------------------------------------------
__device__ __forceinline__ void gemm_core(
    const __half* __restrict__ A, int lda,
    const __half* __restrict__ B, int ldb,
    float* __restrict__ Cf, __half* __restrict__ Ch, int ldc,
    int K, const float* __restrict__ bias, float scale)
{
    extern __shared__ __half smemh[];
    const uint32_t* smem32 = (const uint32_t*)smemh;
    const int tid  = threadIdx.x;
    const int wid  = tid >> 5;
    const int lane = tid & 31;
    const int wm   = wid >> 2;          // 0..1
    const int wn   = wid & 3;           // 0..3
    const int g    = lane >> 2;         // 0..7
    const int c    = lane & 3;          // 0..3
    const int m0   = blockIdx.y * BM;
    const int n0   = blockIdx.x * BN;
    const int NT   = K >> 6;

    float acc[4][4][4];
    #pragma unroll
    for (int i = 0; i < 4; i++)
        #pragma unroll
        for (int j = 0; j < 4; j++)
            #pragma unroll
            for (int r = 0; r < 4; r++) acc[i][j][r] = 0.0f;

    // producer: 2 threads per 64-half row, each copies 32 halves (4 x 16B)
    const int prow = tid >> 1;
    const int pcol = (tid & 1) * 32;            // halves
    const __half* Ag = A + (size_t)(m0 + prow) * lda + pcol;
    const __half* Bg = B + (size_t)(n0 + prow) * ldb + pcol;
    const uint32_t sb = smem_u32(smemh);
    const uint32_t a_dst = sb + (uint32_t)(prow * SH + pcol) * 2;
    const uint32_t b_dst = a_dst + A_TILE_HALVES * 2;

    // prologue: stage 0
    {
        #pragma unroll
        for (int j = 0; j < 4; j++) {
            cp_async16(a_dst + j * 16, Ag + j * 8);
            cp_async16(b_dst + j * 16, Bg + j * 8);
        }
        CP_COMMIT();
    }

    for (int t = 0; t < NT; t++) {
        if (t + 1 < NT) {
            const uint32_t so = (uint32_t)(((t + 1) & 1) * STAGE_HALVES) * 2;
            const __half* ag = Ag + (t + 1) * BK;
            const __half* bg = Bg + (t + 1) * BK;
            #pragma unroll
            for (int j = 0; j < 4; j++) {
                cp_async16(a_dst + so + j * 16, ag + j * 8);
                cp_async16(b_dst + so + j * 16, bg + j * 8);
            }
            CP_COMMIT();
            CP_WAIT(1);
        } else {
            CP_WAIT(0);
        }
        __syncthreads();

        const uint32_t* As32 = smem32 + (t & 1) * (STAGE_HALVES / 2);
        const uint32_t* Bs32 = As32 + A_TILE_HALVES / 2;

        #pragma unroll
        for (int ks = 0; ks < 4; ks++) {          // 4 x k16 per BK=64
            const int kw = ks * 8 + c;            // word offset within row
            uint32_t af[4][4], bf[4][2];
            #pragma unroll
            for (int mt = 0; mt < 4; mt++) {
                const uint32_t* ap = As32 + (wm * 64 + mt * 16 + g) * ROW_WORDS + kw;
                af[mt][0] = ap[0];
                af[mt][1] = ap[8 * ROW_WORDS];
                af[mt][2] = ap[4];
                af[mt][3] = ap[8 * ROW_WORDS + 4];
            }
            #pragma unroll
            for (int nt = 0; nt < 4; nt++) {
                const uint32_t* bp = Bs32 + (wn * 32 + nt * 8 + g) * ROW_WORDS + kw;
                bf[nt][0] = bp[0];
                bf[nt][1] = bp[4];
            }
            #pragma unroll
            for (int mt = 0; mt < 4; mt++)
                #pragma unroll
                for (int nt = 0; nt < 4; nt++)
                    mma_f16(acc[mt][nt], af[mt], bf[nt]);
        }
        __syncthreads();
    }

    // epilogue
    #pragma unroll
    for (int mt = 0; mt < 4; mt++) {
        #pragma unroll
        for (int nt = 0; nt < 4; nt++) {
            const int row0 = m0 + wm * 64 + mt * 16 + g;
            const int col  = n0 + wn * 32 + nt * 8 + 2 * c;
            const float b0 = bias ? bias[col]     : 0.0f;
            const float b1 = bias ? bias[col + 1] : 0.0f;
            #pragma unroll
            for (int h = 0; h < 2; h++) {
                float x0 = acc[mt][nt][2 * h + 0] * scale + b0;
                float x1 = acc[mt][nt][2 * h + 1] * scale + b1;
                const size_t off = (size_t)(row0 + h * 8) * ldc + col;
                if (Ch) {
                    __half2 o = __floats2half2_rn(x0, x1);
                    *(__half2*)(Ch + off) = o;
                } else {
                    float2 o; o.x = x0; o.y = x1;
                    *(float2*)(Cf + off) = o;
                }
            }
        }
    }
}

// ---------------------------------------------------------------------------
// GEMM entry kernels
// ---------------------------------------------------------------------------
__global__ __launch_bounds__(256, 2) void qkv_tc(
    const float* __restrict__ bq, const float* __restrict__ bk,
    const float* __restrict__ bv)
{
    const int z = blockIdx.z;
    const __half* W = g_wh[z];
    const float* bias = (z == 0) ? bq : (z == 1) ? bk : bv;
    __half* O = (z == 0) ? g_qh : (z == 1) ? g_kh : g_vh;
    gemm_core(g_xh, D_MODEL, W, D_MODEL, nullptr, O, FF_DIM, D_MODEL, bias, 1.0f);
}

__global__ __launch_bounds__(256, 2) void scores_tc()
{
    const int b = blockIdx.z;
    gemm_core(g_qh + (size_t)b * SEQ * FF_DIM, FF_DIM,
              g_kh + (size_t)b * SEQ * FF_DIM, FF_DIM,
              g_s + (size_t)b * SEQ * SEQ, nullptr, SEQ,
              FF_DIM, nullptr, ATTN_SCALE);
}

__global__ __launch_bounds__(256, 2) void pv_tc(float* __restrict__ out)
{
    const int b = blockIdx.z;
    gemm_core(g_p   + (size_t)b * SEQ * SEQ,    SEQ,
              g_vTh + (size_t)b * FF_DIM * SEQ, SEQ,
              out + (size_t)b * SEQ * FF_DIM, nullptr, FF_DIM,
              SEQ, nullptr, 1.0f);
}

// ---------------------------------------------------------------------------
// Prep: convert X / W to fp16 (RN) into scratch (8 floats / thread)
// ---------------------------------------------------------------------------
__global__ void cvt_kernel(const float* __restrict__ src, int which, int n8)
{
    __half* dst = (which == 0) ? g_xh : g_wh[which - 1];
    int i = blockIdx.x * blockDim.x + threadIdx.x;
    if (i < n8) {
        float4 v0 = ((const float4*)src)[2 * i];
        float4 v1 = ((const float4*)src)[2 * i + 1];
        __half2 h0 = __floats2half2_rn(v0.x, v0.y);
        __half2 h1 = __floats2half2_rn(v0.z, v0.w);
        __half2 h2 = __floats2half2_rn(v1.x, v1.y);
        __half2 h3 = __floats2half2_rn(v1.z, v1.w);
        uint4 o;
        o.x = *reinterpret_cast<uint32_t*>(&h0);
        o.y = *reinterpret_cast<uint32_t*>(&h1);
        o.z = *reinterpret_cast<uint32_t*>(&h2);
        o.w = *reinterpret_cast<uint32_t*>(&h3);
        ((uint4*)dst)[i] = o;
    }
}

// ---------------------------------------------------------------------------
// V transpose (per batch): g_vTh[b][f][s] = g_vh[b][s][f]
// ---------------------------------------------------------------------------
__global__ void transpose_v()
{
    __shared__ __half t[32][34];
    const int b  = blockIdx.z;
    const int s0 = blockIdx.x * 32;
    const int f0 = blockIdx.y * 32;
    const int tx = threadIdx.x, ty = threadIdx.y;

    #pragma unroll
    for (int i = 0; i < 4; i++) {
        int s = s0 + ty + i * 8;
        t[ty + i * 8][tx] = g_vh[((size_t)b * SEQ + s) * FF_DIM + f0 + tx];
    }
    __syncthreads();
    #pragma unroll
    for (int i = 0; i < 4; i++) {
        int f = f0 + ty + i * 8;
        g_vTh[((size_t)b * FF_DIM + f) * SEQ + s0 + tx] = t[tx][ty + i * 8];
    }
}

// ---------------------------------------------------------------------------
// Row softmax: read fp32 g_s row (2048), write half g_p
// ---------------------------------------------------------------------------
__global__ __launch_bounds__(256) void softmax_kernel()
{
    const int row = blockIdx.x;
    const float* p = g_s + (size_t)row * SEQ;
    __half* q = g_p + (size_t)row * SEQ;
    const int tid  = threadIdx.x;
    const int lane = tid & 31;
    const int wid  = tid >> 5;
    __shared__ float red[32];

    float v[8];
    #pragma unroll
    for (int i = 0; i < 8; i++) v[i] = p[tid + i * 256];

    float m = v[0];
    #pragma unroll
    for (int i = 1; i < 8; i++) m = fmaxf(m, v[i]);
    #pragma unroll
    for (int o = 16; o > 0; o >>= 1) m = fmaxf(m, __shfl_xor_sync(0xffffffffu, m, o));
    if (lane == 0) red[wid] = m;
    __syncthreads();
    if (tid < 32) {
        float t = (lane < 8) ? red[lane] : -3.4e38f;
        #pragma unroll
        for (int o = 4; o > 0; o >>= 1) t = fmaxf(t, __shfl_xor_sync(0xffffffffu, t, o));
        red[lane] = t;
    }
    __syncthreads();
    m = red[0];
    __syncthreads();

    float s = 0.0f;
    #pragma unroll
    for (int i = 0; i < 8; i++) { v[i] = __expf(v[i] - m); s += v[i]; }
    #pragma unroll
    for (int o = 16; o > 0; o >>= 1) s += __shfl_xor_sync(0xffffffffu, s, o);
    if (lane == 0) red[wid] = s;
    __syncthreads();
    if (tid < 32) {
        float t = (lane < 8) ? red[lane] : 0.0f;
        #pragma unroll
        for (int o = 4; o > 0; o >>= 1) t += __shfl_xor_sync(0xffffffffu, t, o);
        red[lane] = t;
    }
    __syncthreads();
    const float inv = 1.0f / red[0];

    #pragma unroll
    for (int i = 0; i < 8; i++) q[tid + i * 256] = __float2half_rn(v[i] * inv);
}

// ---------------------------------------------------------------------------
// Entry point
// ---------------------------------------------------------------------------
extern "C" void kernel_launch(void* const* d_in, const int* in_sizes, int n_in,
                              void* d_out, int out_size)
{
    const float* seq = (const float*)d_in[0];
    const float* Wq  = (const float*)d_in[1];
    const float* bq  = (const float*)d_in[2];
    const float* Wk  = (const float*)d_in[3];
    const float* bk  = (const float*)d_in[4];
    const float* Wv  = (const float*)d_in[5];
    const float* bv  = (const float*)d_in[6];
    float* out = (float*)d_out;

    cudaFuncSetAttribute(qkv_tc,    cudaFuncAttributeMaxDynamicSharedMemorySize, SMEM_BYTES);
    cudaFuncSetAttribute(scores_tc, cudaFuncAttributeMaxDynamicSharedMemorySize, SMEM_BYTES);
    cudaFuncSetAttribute(pv_tc,     cudaFuncAttributeMaxDynamicSharedMemorySize, SMEM_BYTES);

    // 1) convert inputs to fp16 (RN)
    const int nx8 = (M_TOTAL * D_MODEL) / 8;
    const int nw8 = (FF_DIM * D_MODEL) / 8;
    cvt_kernel<<<(nx8 + 255) / 256, 256>>>(seq, 0, nx8);
    cvt_kernel<<<(nw8 + 255) / 256, 256>>>(Wq, 1, nw8);
    cvt_kernel<<<(nw8 + 255) / 256, 256>>>(Wk, 2, nw8);
    cvt_kernel<<<(nw8 + 255) / 256, 256>>>(Wv, 3, nw8);

    // 2) Q/K/V projections
    qkv_tc<<<dim3(FF_DIM / BN, M_TOTAL / BM, 3), 256, SMEM_BYTES>>>(bq, bk, bv);

    // 3) V^T for the PV GEMM
    transpose_v<<<dim3(SEQ / 32, FF_DIM / 32, BATCH), dim3(32, 8)>>>();

    // 4) scores = scale * Q K^T (fp32 out)
    scores_tc<<<dim3(SEQ / BN, SEQ / BM, BATCH), 256, SMEM_BYTES>>>();

    // 5) softmax (half out)
    softmax_kernel<<<M_TOTAL, 256>>>();

    // 6) out = P V
    pv_tc<<<dim3(FF_DIM / BN, SEQ / BM, BATCH), 256, SMEM_BYTES>>>(out);
}

// round 12
// speedup vs baseline: 2.0529x; 1.0089x over previous
#include <cuda_runtime.h>
#include <cuda_fp16.h>
#include <cstdint>
#include <cstddef>

#define D_MODEL 1024
#define FF_DIM  1024
#define BATCH   8
#define SEQ     2048
#define M_TOTAL (BATCH * SEQ)      // 16384
#define ATTN_SCALE 0.03125f

// ---- GEMM tile config (fp16 m16n8k16) --------------------------------------
#define BM 128
#define BN 128
#define BK 64
#define STAGES 3
#define SH 72                                 // halves per smem row (64 data + 8 pad)
#define ROW_WORDS 36                          // 32-bit words per row
#define A_TILE_HALVES (128 * SH)              // 9216 halves (18432 B)
#define STAGE_HALVES (2 * A_TILE_HALVES)      // A + B
#define SMEM_BYTES (STAGES * STAGE_HALVES * 2)  // 110592 B

// ---- scratch (device globals; no runtime allocation) -----------------------
__device__ __half g_xh[(size_t)M_TOTAL * D_MODEL];
__device__ __half g_wh[3][(size_t)FF_DIM * D_MODEL];
__device__ __half g_qh[(size_t)M_TOTAL * FF_DIM];
__device__ __half g_kh[(size_t)M_TOTAL * FF_DIM];
__device__ __half g_vTh[(size_t)BATCH * FF_DIM * SEQ];   // V^T, written by qkv epilogue
__device__ float  g_s[(size_t)BATCH * SEQ * SEQ];        // fp32 scores
__device__ __half g_p[(size_t)BATCH * SEQ * SEQ];        // half probabilities

// ---- helpers ---------------------------------------------------------------
__device__ __forceinline__ uint32_t smem_u32(const void* p) {
    uint32_t a;
    asm("{ .reg .u64 t; cvta.to.shared.u64 t, %1; cvt.u32.u64 %0, t; }"
        : "=r"(a) : "l"(p));
    return a;
}

__device__ __forceinline__ void cp_async16(uint32_t dst, const void* src) {
    asm volatile("cp.async.cg.shared.global [%0], [%1], 16;"
                 :: "r"(dst), "l"(src));
}
#define CP_COMMIT() asm volatile("cp.async.commit_group;" ::: "memory")
#define CP_WAIT(n)  asm volatile("cp.async.wait_group %0;" :: "n"(n) : "memory")

__device__ __forceinline__ void mma_f16(float* d, const uint32_t* a, const uint32_t* b) {
    asm volatile(
        "mma.sync.aligned.m16n8k16.row.col.f32.f16.f16.f32 "
        "{%0,%1,%2,%3}, {%4,%5,%6,%7}, {%8,%9}, {%0,%1,%2,%3};"
        : "+f"(d[0]), "+f"(d[1]), "+f"(d[2]), "+f"(d[3])
        : "r"(a[0]), "r"(a[1]), "r"(a[2]), "r"(a[3]), "r"(b[0]), "r"(b[1]));
}

// Output modes
#define OUT_F32  0   // fp32, normal layout
#define OUT_F16  1   // half, normal layout
#define OUT_F16T 2   // half, transposed per-batch layout (V^T)

// ---------------------------------------------------------------------------
// fp16 tensor-core GEMM (NT): C[m,n] = scale * sum_k A[m,k]*B[n,k] + bias[n]
// A: [M,K] row-major half, B: [N,K] row-major half. 256 threads, 8 warps
// (2m x 4n), warp tile 64x32, BK=64, 3-stage cp.async pipeline.
// ---------------------------------------------------------------------------
__device__ __forceinline__ void gemm_core(
    const __half* __restrict__ A, int lda,
    const __half* __restrict__ B, int ldb,
    float* __restrict__ Cf, __half* __restrict__ Ch, int ldc,
    int K, const float* __restrict__ bias, float scale, int mode)
{
    extern __shared__ __half smemh[];
    const uint32_t* smem32 = (const uint32_t*)smemh;
    const int tid  = threadIdx.x;
    const int wid  = tid >> 5;
    const int lane = tid & 31;
    const int wm   = wid >> 2;          // 0..1
    const int wn   = wid & 3;           // 0..3
    const int g    = lane >> 2;         // 0..7
    const int c    = lane & 3;          // 0..3
    const int m0   = blockIdx.y * BM;
    const int n0   = blockIdx.x * BN;
    const int NT   = K >> 6;

    float acc[4][4][4];
    #pragma unroll
    for (int i = 0; i < 4; i++)
        #pragma unroll
        for (int j = 0; j < 4; j++)
            #pragma unroll
            for (int r = 0; r < 4; r++) acc[i][j][r] = 0.0f;

    // producer: 2 threads per 64-half row, each copies 32 halves (4 x 16B)
    const int prow = tid >> 1;
    const int pcol = (tid & 1) * 32;            // halves
    const __half* Ag = A + (size_t)(m0 + prow) * lda + pcol;
    const __half* Bg = B + (size_t)(n0 + prow) * ldb + pcol;
    const uint32_t sb = smem_u32(smemh);
    const uint32_t a_dst = sb + (uint32_t)(prow * SH + pcol) * 2;
    const uint32_t b_dst = a_dst + A_TILE_HALVES * 2;

    // prologue: stages 0 and 1 (each its own commit group)
    #pragma unroll
    for (int s = 0; s < 2; s++) {
        if (s < NT) {
            const uint32_t so = (uint32_t)(s * STAGE_HALVES) * 2;
            const __half* ag = Ag + s * BK;
            const __half* bg = Bg + s * BK;
            #pragma unroll
            for (int j = 0; j < 4; j++) {
                cp_async16(a_dst + so + j * 16, ag + j * 8);
                cp_async16(b_dst + so + j * 16, bg + j * 8);
            }
        }
        CP_COMMIT();
    }

    for (int t = 0; t < NT; t++) {
        // issue load for stage t+2 (or an empty group to keep accounting static)
        if (t + 2 < NT) {
            const int st = (t + 2) % STAGES;
            const uint32_t so = (uint32_t)(st * STAGE_HALVES) * 2;
            const __half* ag = Ag + (t + 2) * BK;
            const __half* bg = Bg + (t + 2) * BK;
            #pragma unroll
            for (int j = 0; j < 4; j++) {
                cp_async16(a_dst + so + j * 16, ag + j * 8);
                cp_async16(b_dst + so + j * 16, bg + j * 8);
            }
        }
        CP_COMMIT();
        CP_WAIT(2);           // group for stage t is complete
        __syncthreads();

        const int cs = t % STAGES;
        const uint32_t* As32 = smem32 + cs * (STAGE_HALVES / 2);
        const uint32_t* Bs32 = As32 + A_TILE_HALVES / 2;

        #pragma unroll
        for (int ks = 0; ks < 4; ks++) {          // 4 x k16 per BK=64
            const int kw = ks * 8 + c;            // word offset within row
            uint32_t af[4][4], bf[4][2];
            #pragma unroll
            for (int mt = 0; mt < 4; mt++) {
                const uint32_t* ap = As32 + (wm * 64 + mt * 16 + g) * ROW_WORDS + kw;
                af[mt][0] = ap[0];
                af[mt][1] = ap[8 * ROW_WORDS];
                af[mt][2] = ap[4];
                af[mt][3] = ap[8 * ROW_WORDS + 4];
            }
            #pragma unroll
            for (int nt = 0; nt < 4; nt++) {
                const uint32_t* bp = Bs32 + (wn * 32 + nt * 8 + g) * ROW_WORDS + kw;
                bf[nt][0] = bp[0];
                bf[nt][1] = bp[4];
            }
            #pragma unroll
            for (int mt = 0; mt < 4; mt++)
                #pragma unroll
                for (int nt = 0; nt < 4; nt++)
                    mma_f16(acc[mt][nt], af[mt], bf[nt]);
        }
        __syncthreads();
    }

    // epilogue
    #pragma unroll
    for (int mt = 0; mt < 4; mt++) {
        #pragma unroll
        for (int nt = 0; nt < 4; nt++) {
            const int row0 = m0 + wm * 64 + mt * 16 + g;
            const int col  = n0 + wn * 32 + nt * 8 + 2 * c;
            const float b0 = bias ? bias[col]     : 0.0f;
            const float b1 = bias ? bias[col + 1] : 0.0f;
            #pragma unroll
            for (int h = 0; h < 2; h++) {
                float x0 = acc[mt][nt][2 * h + 0] * scale + b0;
                float x1 = acc[mt][nt][2 * h + 1] * scale + b1;
                const int row = row0 + h * 8;
                if (mode == OUT_F16T) {
                    // V^T: g_vTh[b][f][s] with b = row>>11, s = row&2047, f = col
                    const int bb = row >> 11;
                    const int ss = row & 2047;
                    __half* base = Ch + ((size_t)bb * FF_DIM) * SEQ;
                    base[(size_t)col       * SEQ + ss] = __float2half_rn(x0);
                    base[(size_t)(col + 1) * SEQ + ss] = __float2half_rn(x1);
                } else if (mode == OUT_F16) {
                    __half2 o = __floats2half2_rn(x0, x1);
                    *(__half2*)(Ch + (size_t)row * ldc + col) = o;
                } else {
                    float2 o; o.x = x0; o.y = x1;
                    *(float2*)(Cf + (size_t)row * ldc + col) = o;
                }
            }
        }
    }
}

// ---------------------------------------------------------------------------
// GEMM entry kernels
// ---------------------------------------------------------------------------
__global__ __launch_bounds__(256, 2) void qkv_tc(
    const float* __restrict__ bq, const float* __restrict__ bk,
    const float* __restrict__ bv)
{
    const int z = blockIdx.z;
    const __half* W = g_wh[z];
    const float* bias = (z == 0) ? bq : (z == 1) ? bk : bv;
    if (z == 2) {
        gemm_core(g_xh, D_MODEL, W, D_MODEL, nullptr, g_vTh, FF_DIM,
                  D_MODEL, bias, 1.0f, OUT_F16T);
    } else {
        __half* O = (z == 0) ? g_qh : g_kh;
        gemm_core(g_xh, D_MODEL, W, D_MODEL, nullptr, O, FF_DIM,
                  D_MODEL, bias, 1.0f, OUT_F16);
    }
}

__global__ __launch_bounds__(256, 2) void scores_tc()
{
    const int b = blockIdx.z;
    gemm_core(g_qh + (size_t)b * SEQ * FF_DIM, FF_DIM,
              g_kh + (size_t)b * SEQ * FF_DIM, FF_DIM,
              g_s + (size_t)b * SEQ * SEQ, nullptr, SEQ,
              FF_DIM, nullptr, ATTN_SCALE, OUT_F32);
}

__global__ __launch_bounds__(256, 2) void pv_tc(float* __restrict__ out)
{
    const int b = blockIdx.z;
    gemm_core(g_p   + (size_t)b * SEQ * SEQ,    SEQ,
              g_vTh + (size_t)b * FF_DIM * SEQ, SEQ,
              out + (size_t)b * SEQ * FF_DIM, nullptr, FF_DIM,
              SEQ, nullptr, 1.0f, OUT_F32);
}

// ---------------------------------------------------------------------------
// Prep: convert X / W to fp16 (RN) into scratch (8 floats / thread)
// ---------------------------------------------------------------------------
__global__ void cvt_kernel(const float* __restrict__ src, int which, int n8)
{
    __half* dst = (which == 0) ? g_xh : g_wh[which - 1];
    int i = blockIdx.x * blockDim.x + threadIdx.x;
    if (i < n8) {
        float4 v0 = ((const float4*)src)[2 * i];
        float4 v1 = ((const float4*)src)[2 * i + 1];
        __half2 h0 = __floats2half2_rn(v0.x, v0.y);
        __half2 h1 = __floats2half2_rn(v0.z, v0.w);
        __half2 h2 = __floats2half2_rn(v1.x, v1.y);
        __half2 h3 = __floats2half2_rn(v1.z, v1.w);
        uint4 o;
        o.x = *reinterpret_cast<uint32_t*>(&h0);
        o.y = *reinterpret_cast<uint32_t*>(&h1);
        o.z = *reinterpret_cast<uint32_t*>(&h2);
        o.w = *reinterpret_cast<uint32_t*>(&h3);
        ((uint4*)dst)[i] = o;
    }
}

// ---------------------------------------------------------------------------
// Row softmax: read fp32 g_s row (2048, float4), write half g_p (uint2)
// ---------------------------------------------------------------------------
__global__ __launch_bounds__(256) void softmax_kernel()
{
    const int row = blockIdx.x;
    const float4* p4 = (const float4*)(g_s + (size_t)row * SEQ);
    uint2* q2 = (uint2*)(g_p + (size_t)row * SEQ);
    const int tid  = threadIdx.x;
    const int lane = tid & 31;
    const int wid  = tid >> 5;
    __shared__ float red[32];

    float4 va = p4[tid];
    float4 vb = p4[tid + 256];

    float m = fmaxf(fmaxf(fmaxf(va.x, va.y), fmaxf(va.z, va.w)),
                    fmaxf(fmaxf(vb.x, vb.y), fmaxf(vb.z, vb.w)));
    #pragma unroll
    for (int o = 16; o > 0; o >>= 1) m = fmaxf(m, __shfl_xor_sync(0xffffffffu, m, o));
    if (lane == 0) red[wid] = m;
    __syncthreads();
    if (tid < 32) {
        float t = (lane < 8) ? red[lane] : -3.4e38f;
        #pragma unroll
        for (int o = 4; o > 0; o >>= 1) t = fmaxf(t, __shfl_xor_sync(0xffffffffu, t, o));
        red[lane] = t;
    }
    __syncthreads();
    m = red[0];
    __syncthreads();

    va.x = __expf(va.x - m); va.y = __expf(va.y - m);
    va.z = __expf(va.z - m); va.w = __expf(va.w - m);
    vb.x = __expf(vb.x - m); vb.y = __expf(vb.y - m);
    vb.z = __expf(vb.z - m); vb.w = __expf(vb.w - m);
    float s = (va.x + va.y + va.z + va.w) + (vb.x + vb.y + vb.z + vb.w);
    #pragma unroll
    for (int o = 16; o > 0; o >>= 1) s += __shfl_xor_sync(0xffffffffu, s, o);
    if (lane == 0) red[wid] = s;
    __syncthreads();
    if (tid < 32) {
        float t = (lane < 8) ? red[lane] : 0.0f;
        #pragma unroll
        for (int o = 4; o > 0; o >>= 1) t += __shfl_xor_sync(0xffffffffu, t, o);
        red[lane] = t;
    }
    __syncthreads();
    const float inv = 1.0f / red[0];

    __half2 a0 = __floats2half2_rn(va.x * inv, va.y * inv);
    __half2 a1 = __floats2half2_rn(va.z * inv, va.w * inv);
    __half2 b0 = __floats2half2_rn(vb.x * inv, vb.y * inv);
    __half2 b1 = __floats2half2_rn(vb.z * inv, vb.w * inv);
    uint2 oa, ob;
    oa.x = *reinterpret_cast<uint32_t*>(&a0);
    oa.y = *reinterpret_cast<uint32_t*>(&a1);
    ob.x = *reinterpret_cast<uint32_t*>(&b0);
    ob.y = *reinterpret_cast<uint32_t*>(&b1);
    q2[tid] = oa;
    q2[tid + 256] = ob;
}

// ---------------------------------------------------------------------------
// Entry point
// ---------------------------------------------------------------------------
extern "C" void kernel_launch(void* const* d_in, const int* in_sizes, int n_in,
                              void* d_out, int out_size)
{
    const float* seq = (const float*)d_in[0];
    const float* Wq  = (const float*)d_in[1];
    const float* bq  = (const float*)d_in[2];
    const float* Wk  = (const float*)d_in[3];
    const float* bk  = (const float*)d_in[4];
    const float* Wv  = (const float*)d_in[5];
    const float* bv  = (const float*)d_in[6];
    float* out = (float*)d_out;

    cudaFuncSetAttribute(qkv_tc,    cudaFuncAttributeMaxDynamicSharedMemorySize, SMEM_BYTES);
    cudaFuncSetAttribute(scores_tc, cudaFuncAttributeMaxDynamicSharedMemorySize, SMEM_BYTES);
    cudaFuncSetAttribute(pv_tc,     cudaFuncAttributeMaxDynamicSharedMemorySize, SMEM_BYTES);

    // 1) convert inputs to fp16 (RN)
    const int nx8 = (M_TOTAL * D_MODEL) / 8;
    const int nw8 = (FF_DIM * D_MODEL) / 8;
    cvt_kernel<<<(nx8 + 255) / 256, 256>>>(seq, 0, nx8);
    cvt_kernel<<<(nw8 + 255) / 256, 256>>>(Wq, 1, nw8);
    cvt_kernel<<<(nw8 + 255) / 256, 256>>>(Wk, 2, nw8);
    cvt_kernel<<<(nw8 + 255) / 256, 256>>>(Wv, 3, nw8);

    // 2) Q/K/V projections (V written transposed directly)
    qkv_tc<<<dim3(FF_DIM / BN, M_TOTAL / BM, 3), 256, SMEM_BYTES>>>(bq, bk, bv);

    // 3) scores = scale * Q K^T (fp32 out)
    scores_tc<<<dim3(SEQ / BN, SEQ / BM, BATCH), 256, SMEM_BYTES>>>();

    // 4) softmax (half out)
    softmax_kernel<<<M_TOTAL, 256>>>();

    // 5) out = P V
    pv_tc<<<dim3(FF_DIM / BN, SEQ / BM, BATCH), 256, SMEM_BYTES>>>(out);
}